// round 8
// baseline (speedup 1.0000x reference)
#include <cuda_runtime.h>
#include <cstdint>
#include <math.h>

#define BB 2
#define SS 2048
#define HIDN 1280
#define NH 20
#define HD 64

// Scratch (alloc-free rule: __device__ globals)
__device__ float g_Q[BB*NH*SS*HD];
__device__ float g_K[BB*NH*SS*HD];
__device__ float g_V[BB*NH*SS*HD];
__device__ float g_X[BB*SS*HIDN];      // tf32-rounded hidden states
__device__ float g_W[3*HIDN*HIDN];     // tf32-rounded Wq|Wk|Wv
__device__ float g_cos[SS*32];
__device__ float g_sin[SS*32];

// ---------------------------------------------------------------------------
// RoPE cos/sin table
// ---------------------------------------------------------------------------
__global__ void sincos_kernel() {
    int idx = blockIdx.x * blockDim.x + threadIdx.x;
    if (idx >= SS * 32) return;
    int j = idx & 31;
    int s = idx >> 5;
    double invf = exp(-((double)j / 32.0) * log(10000.0));
    double a = (double)s * invf;
    g_cos[idx] = (float)cos(a);
    g_sin[idx] = (float)sin(a);
}

// ---------------------------------------------------------------------------
// tf32 helpers
// ---------------------------------------------------------------------------
__device__ __forceinline__ float to_tf32(float x) {
    float r;
    asm("cvt.rna.tf32.f32 %0, %1;" : "=f"(r) : "f"(x));
    return r;
}

__device__ __forceinline__ void mma_tf32(float c[4], const float a[4],
                                         float b0, float b1) {
    asm volatile(
        "mma.sync.aligned.m16n8k8.row.col.f32.tf32.tf32.f32 "
        "{%0,%1,%2,%3}, {%4,%5,%6,%7}, {%8,%9}, {%0,%1,%2,%3};"
        : "+f"(c[0]), "+f"(c[1]), "+f"(c[2]), "+f"(c[3])
        : "r"(__float_as_uint(a[0])), "r"(__float_as_uint(a[1])),
          "r"(__float_as_uint(a[2])), "r"(__float_as_uint(a[3])),
          "r"(__float_as_uint(b0)),  "r"(__float_as_uint(b1)));
}

__device__ __forceinline__ void cp16(unsigned int dst, const void* src) {
    asm volatile("cp.async.cg.shared.global [%0], [%1], 16;\n"
                 :: "r"(dst), "l"(src));
}
__device__ __forceinline__ void cp_commit() {
    asm volatile("cp.async.commit_group;\n" ::: "memory");
}
template <int N>
__device__ __forceinline__ void cp_wait() {
    asm volatile("cp.async.wait_group %0;\n" :: "n"(N) : "memory");
}

// ---------------------------------------------------------------------------
// Prep: round X and the 3 weight matrices to tf32 (rna) into scratch.
// ---------------------------------------------------------------------------
#define NX4 (BB*SS*HIDN/4)
#define NW4 (HIDN*HIDN/4)

__global__ __launch_bounds__(256) void prep_tf32(
    const float4* __restrict__ X,
    const float4* __restrict__ Wq,
    const float4* __restrict__ Wk,
    const float4* __restrict__ Wv)
{
    int i = blockIdx.x * blockDim.x + threadIdx.x;
    float4 v;
    float4* dst;
    if (i < NX4) {
        v = X[i]; dst = ((float4*)g_X) + i;
    } else if (i < NX4 + NW4) {
        int j = i - NX4; v = Wq[j]; dst = ((float4*)g_W) + j;
    } else if (i < NX4 + 2 * NW4) {
        int j = i - NX4 - NW4; v = Wk[j]; dst = ((float4*)g_W) + NW4 + j;
    } else {
        int j = i - NX4 - 2 * NW4; v = Wv[j]; dst = ((float4*)g_W) + 2 * NW4 + j;
    }
    v.x = to_tf32(v.x); v.y = to_tf32(v.y);
    v.z = to_tf32(v.z); v.w = to_tf32(v.w);
    *dst = v;
}

// ---------------------------------------------------------------------------
// Fused QKV projection GEMM — tf32 mma + cp.async 2-stage pipeline.
// ---------------------------------------------------------------------------
#define QAS 4608
#define QBS 4352
#define QKV_SMEM_BYTES (17920 * 4)

__global__ __launch_bounds__(256, 2) void qkv_gemm_tf32(
    const float* __restrict__ bq,
    const float* __restrict__ bk,
    const float* __restrict__ bv)
{
    extern __shared__ float sm[];

    const int n0g   = blockIdx.x * 128;
    const int m0    = blockIdx.y * 128;
    const int which = n0g / HIDN;
    const int ncol0 = n0g % HIDN;

    const float* Wp   = g_W + (size_t)which * HIDN * HIDN;
    const float* bias = (which == 0) ? bq : (which == 1 ? bk : bv);
    float*       Out  = (which == 0) ? g_Q : (which == 1 ? g_K : g_V);

    const int tid  = threadIdx.x;
    const int lane = tid & 31;
    const int warp = tid >> 5;
    const int wm   = (warp & 1) * 64;
    const int wn   = (warp >> 1) * 32;
    const int g    = lane >> 2;
    const int t4   = lane & 3;

    const unsigned int sbase = (unsigned int)__cvta_generic_to_shared(sm);
    const int a_r  = tid >> 3;
    const int a_k  = (tid & 7) * 4;
    const int b_n  = lane * 4;

    float acc[4][4][4];
    #pragma unroll
    for (int mt = 0; mt < 4; mt++)
        #pragma unroll
        for (int nt = 0; nt < 4; nt++)
            #pragma unroll
            for (int i = 0; i < 4; i++) acc[mt][nt][i] = 0.0f;

    {
        #pragma unroll
        for (int p = 0; p < 4; p++) {
            int r = a_r + 32 * p;
            cp16(sbase + (r * 36 + a_k) * 4, g_X + (m0 + r) * HIDN + a_k);
        }
        #pragma unroll
        for (int p = 0; p < 4; p++) {
            int kk = warp + 8 * p;
            cp16(sbase + (9216 + kk * 136 + b_n) * 4, Wp + kk * HIDN + ncol0 + b_n);
        }
        cp_commit();
    }

    for (int kt = 0; kt < HIDN / 32; kt++) {
        const int buf = kt & 1;
        cp_wait<0>();
        __syncthreads();

        if (kt < HIDN / 32 - 1) {
            const int k0 = (kt + 1) * 32;
            const int ao = (buf ^ 1) * QAS;
            const int bo = 9216 + (buf ^ 1) * QBS;
            #pragma unroll
            for (int p = 0; p < 4; p++) {
                int r = a_r + 32 * p;
                cp16(sbase + (ao + r * 36 + a_k) * 4,
                     g_X + (m0 + r) * HIDN + k0 + a_k);
            }
            #pragma unroll
            for (int p = 0; p < 4; p++) {
                int kk = warp + 8 * p;
                cp16(sbase + (bo + kk * 136 + b_n) * 4,
                     Wp + (k0 + kk) * HIDN + ncol0 + b_n);
            }
            cp_commit();
        }

        const float* A  = sm + buf * QAS;
        const float* Bt = sm + 9216 + buf * QBS;

        #pragma unroll
        for (int kc = 0; kc < 4; kc++) {
            const int kr = kc * 8;
            float a[4][4];
            #pragma unroll
            for (int mt = 0; mt < 4; mt++) {
                int mr = wm + mt * 16;
                a[mt][0] = A[(mr + g    ) * 36 + kr + t4    ];
                a[mt][1] = A[(mr + g + 8) * 36 + kr + t4    ];
                a[mt][2] = A[(mr + g    ) * 36 + kr + t4 + 4];
                a[mt][3] = A[(mr + g + 8) * 36 + kr + t4 + 4];
            }
            #pragma unroll
            for (int nt = 0; nt < 4; nt++) {
                float b0 = Bt[(kr + t4    ) * 136 + wn + nt * 8 + g];
                float b1 = Bt[(kr + t4 + 4) * 136 + wn + nt * 8 + g];
                #pragma unroll
                for (int mt = 0; mt < 4; mt++)
                    mma_tf32(acc[mt][nt], a[mt], b0, b1);
            }
        }
    }

    #pragma unroll
    for (int mt = 0; mt < 4; mt++) {
        #pragma unroll
        for (int nt = 0; nt < 4; nt++) {
            int col = ncol0 + wn + nt * 8 + t4 * 2;
            int h = col >> 6;
            int d = col & 63;
            float bi0 = bias[col];
            float bi1 = bias[col + 1];
            #pragma unroll
            for (int rh = 0; rh < 2; rh++) {
                int m = m0 + wm + mt * 16 + g + rh * 8;
                int b = m >> 11;
                int s = m & 2047;
                float2 v;
                v.x = acc[mt][nt][rh * 2 + 0] + bi0;
                v.y = acc[mt][nt][rh * 2 + 1] + bi1;
                *(float2*)&Out[(((b * NH + h) * SS) + s) * HD + d] = v;
            }
        }
    }
}

// ---------------------------------------------------------------------------
// RoPE (+ query scaling). Pre-rounds Q, K, V to tf32.
// ---------------------------------------------------------------------------
__global__ __launch_bounds__(256) void rope_kernel() {
    int idx = blockIdx.x * blockDim.x + threadIdx.x;
    int j  = idx & 31;
    int s  = (idx >> 5) & (SS - 1);
    int bh = idx >> 16;
    float c  = g_cos[(s << 5) + j];
    float sn = g_sin[(s << 5) + j];
    int base = (bh * SS + s) * HD;
    const float scale = 0.125f;

    float q1 = g_Q[base + j], q2 = g_Q[base + j + 32];
    g_Q[base + j]      = to_tf32((q1 * c - q2 * sn) * scale);
    g_Q[base + j + 32] = to_tf32((q2 * c + q1 * sn) * scale);

    float k1 = g_K[base + j], k2 = g_K[base + j + 32];
    g_K[base + j]      = to_tf32(k1 * c - k2 * sn);
    g_K[base + j + 32] = to_tf32(k2 * c + k1 * sn);

    g_V[base + j]      = to_tf32(g_V[base + j]);
    g_V[base + j + 32] = to_tf32(g_V[base + j + 32]);
}

// ---------------------------------------------------------------------------
// Flash attention, tf32 mma, cp.async double-buffered K/V.
// BQ=128: 4 warps, each owns TWO m16 tiles (rows 32w..32w+31); BKV=32.
// mt innermost so each K/V fragment LDS feeds 2 mma (halves crossbar traffic).
// Dynamic smem (floats):
//   [0,     8704)  Qs[128][68] staging, reused as Ps[128][36]
//   [8704, 10880)  K buf0 [32][68]
//   [10880,13056)  K buf1 [32][68]
//   [13056,15360)  V buf0 [32][72]
//   [15360,17664)  V buf1 [32][72]
// ---------------------------------------------------------------------------
#define OFF_K0 8704
#define OFF_V0 13056
#define KBUF 2176
#define VBUF 2304
#define ATTN_SMEM_BYTES (17664 * 4)

__global__ __launch_bounds__(128) void attn_tf32(
    const float* __restrict__ mask, float* __restrict__ out)
{
    extern __shared__ float sm[];
    float (*Ps)[36] = (float(*)[36])sm;

    const int bh = blockIdx.y;
    const int b  = bh / NH;
    const int h  = bh % NH;
    const int q0 = blockIdx.x * 128;

    const float* Qb = g_Q + (size_t)bh * SS * HD;
    const float* Kb = g_K + (size_t)bh * SS * HD;
    const float* Vb = g_V + (size_t)bh * SS * HD;
    const float2* mk2 = (const float2*)(mask + b * SS);

    const int tid  = threadIdx.x;
    const int lane = tid & 31;
    const int warp = tid >> 5;
    const int g    = lane >> 2;
    const int t4   = lane & 3;
    const int wm   = warp * 32;

    const unsigned int sbase = (unsigned int)__cvta_generic_to_shared(sm);
    const int c_row = tid >> 2;          // 0..31
    const int c_c4  = (tid & 3) << 2;    // 0,4,8,12 (+16p covers 64 cols)

    // Prologue: issue tile 0 K/V copies into buffer 0
    {
        #pragma unroll
        for (int p = 0; p < 4; p++) {
            int c = c_c4 + p * 16;
            cp16(sbase + (OFF_K0 + c_row * 68 + c) * 4, Kb + c_row * HD + c);
            cp16(sbase + (OFF_V0 + c_row * 72 + c) * 4, Vb + c_row * HD + c);
        }
        cp_commit();
    }

    // Stage Q (128 x 64, already tf32-rounded)
    for (int i = tid; i < 2048; i += 128) {
        int r = i >> 4, c = (i & 15) << 2;
        *(float4*)&sm[r * 68 + c] = *(const float4*)&Qb[(q0 + r) * HD + c];
    }
    __syncthreads();

    // Hoist Q fragments for both m16 tiles
    float qf[2][8][4];
    #pragma unroll
    for (int mt = 0; mt < 2; mt++) {
        int mr = wm + mt * 16;
        #pragma unroll
        for (int kc = 0; kc < 8; kc++) {
            int kr = kc * 8;
            qf[mt][kc][0] = sm[(mr + g    ) * 68 + kr + t4    ];
            qf[mt][kc][1] = sm[(mr + g + 8) * 68 + kr + t4    ];
            qf[mt][kc][2] = sm[(mr + g    ) * 68 + kr + t4 + 4];
            qf[mt][kc][3] = sm[(mr + g + 8) * 68 + kr + t4 + 4];
        }
    }

    float oacc[2][8][4];
    #pragma unroll
    for (int mt = 0; mt < 2; mt++)
        #pragma unroll
        for (int dt = 0; dt < 8; dt++)
            #pragma unroll
            for (int i = 0; i < 4; i++) oacc[mt][dt][i] = 0.0f;
    float mrow[2][2] = {{-1e30f, -1e30f}, {-1e30f, -1e30f}};
    float lrow[2][2] = {{0.0f, 0.0f}, {0.0f, 0.0f}};

    for (int it = 0; it < SS / 32; it++) {
        const int buf = it & 1;
        cp_wait<0>();
        __syncthreads();   // buf visible + everyone done reading buf^1

        if (it < SS / 32 - 1) {
            const float* Kn = Kb + (it + 1) * 32 * HD;
            const float* Vn = Vb + (it + 1) * 32 * HD;
            int ko = OFF_K0 + (buf ^ 1) * KBUF;
            int vo = OFF_V0 + (buf ^ 1) * VBUF;
            #pragma unroll
            for (int p = 0; p < 4; p++) {
                int c = c_c4 + p * 16;
                cp16(sbase + (ko + c_row * 68 + c) * 4, Kn + c_row * HD + c);
                cp16(sbase + (vo + c_row * 72 + c) * 4, Vn + c_row * HD + c);
            }
            cp_commit();
        }

        const float* Kt = sm + OFF_K0 + buf * KBUF;
        const float* Vt = sm + OFF_V0 + buf * VBUF;

        // ---- S = Q @ K^T (m32 x n32 per warp; K frag shared by both m16) ----
        float sc[2][4][4];
        #pragma unroll
        for (int mt = 0; mt < 2; mt++)
            #pragma unroll
            for (int nt = 0; nt < 4; nt++)
                #pragma unroll
                for (int i = 0; i < 4; i++) sc[mt][nt][i] = 0.0f;

        #pragma unroll
        for (int kc = 0; kc < 8; kc++) {
            int kr = kc * 8;
            #pragma unroll
            for (int nt = 0; nt < 4; nt++) {
                float b0 = Kt[(nt * 8 + g) * 68 + kr + t4    ];
                float b1 = Kt[(nt * 8 + g) * 68 + kr + t4 + 4];
                mma_tf32(sc[0][nt], qf[0][kc], b0, b1);
                mma_tf32(sc[1][nt], qf[1][kc], b0, b1);
            }
        }

        // ---- mask + online softmax (per m16 tile) ----
        const int k0 = it * 32;
        #pragma unroll
        for (int nt = 0; nt < 4; nt++) {
            float2 mv = __ldg(&mk2[(k0 + nt * 8) / 2 + t4]);
            #pragma unroll
            for (int mt = 0; mt < 2; mt++) {
                sc[mt][nt][0] += mv.x; sc[mt][nt][1] += mv.y;
                sc[mt][nt][2] += mv.x; sc[mt][nt][3] += mv.y;
            }
        }

        #pragma unroll
        for (int mt = 0; mt < 2; mt++) {
            float rx0 = -1e30f, rx1 = -1e30f;
            #pragma unroll
            for (int nt = 0; nt < 4; nt++) {
                rx0 = fmaxf(rx0, fmaxf(sc[mt][nt][0], sc[mt][nt][1]));
                rx1 = fmaxf(rx1, fmaxf(sc[mt][nt][2], sc[mt][nt][3]));
            }
            rx0 = fmaxf(rx0, __shfl_xor_sync(0xffffffffu, rx0, 1));
            rx0 = fmaxf(rx0, __shfl_xor_sync(0xffffffffu, rx0, 2));
            rx1 = fmaxf(rx1, __shfl_xor_sync(0xffffffffu, rx1, 1));
            rx1 = fmaxf(rx1, __shfl_xor_sync(0xffffffffu, rx1, 2));

            float m0n = fmaxf(mrow[mt][0], rx0);
            float m1n = fmaxf(mrow[mt][1], rx1);
            float c0 = __expf(mrow[mt][0] - m0n);
            float c1 = __expf(mrow[mt][1] - m1n);
            mrow[mt][0] = m0n; mrow[mt][1] = m1n;

            float rs0 = 0.0f, rs1 = 0.0f;
            #pragma unroll
            for (int nt = 0; nt < 4; nt++) {
                float p0 = to_tf32(__expf(sc[mt][nt][0] - m0n));
                float p1 = to_tf32(__expf(sc[mt][nt][1] - m0n));
                float p2 = to_tf32(__expf(sc[mt][nt][2] - m1n));
                float p3 = to_tf32(__expf(sc[mt][nt][3] - m1n));
                rs0 += p0 + p1;
                rs1 += p2 + p3;
                *(float2*)&Ps[wm + mt * 16 + g    ][nt * 8 + 2 * t4] = make_float2(p0, p1);
                *(float2*)&Ps[wm + mt * 16 + g + 8][nt * 8 + 2 * t4] = make_float2(p2, p3);
            }
            rs0 += __shfl_xor_sync(0xffffffffu, rs0, 1);
            rs0 += __shfl_xor_sync(0xffffffffu, rs0, 2);
            rs1 += __shfl_xor_sync(0xffffffffu, rs1, 1);
            rs1 += __shfl_xor_sync(0xffffffffu, rs1, 2);
            lrow[mt][0] = lrow[mt][0] * c0 + rs0;
            lrow[mt][1] = lrow[mt][1] * c1 + rs1;

            #pragma unroll
            for (int dt = 0; dt < 8; dt++) {
                oacc[mt][dt][0] *= c0; oacc[mt][dt][1] *= c0;
                oacc[mt][dt][2] *= c1; oacc[mt][dt][3] *= c1;
            }
        }
        __syncwarp();   // Ps rows are warp-private

        // ---- O += P @ V (m32 x n64, k32; V frag shared by both m16) ----
        #pragma unroll
        for (int kc = 0; kc < 4; kc++) {
            int kr = kc * 8;
            float pa[2][4];
            #pragma unroll
            for (int mt = 0; mt < 2; mt++) {
                int mr = wm + mt * 16;
                pa[mt][0] = Ps[mr + g    ][kr + t4    ];
                pa[mt][1] = Ps[mr + g + 8][kr + t4    ];
                pa[mt][2] = Ps[mr + g    ][kr + t4 + 4];
                pa[mt][3] = Ps[mr + g + 8][kr + t4 + 4];
            }
            #pragma unroll
            for (int dt = 0; dt < 8; dt++) {
                float b0 = Vt[(kr + t4    ) * 72 + dt * 8 + g];
                float b1 = Vt[(kr + t4 + 4) * 72 + dt * 8 + g];
                mma_tf32(oacc[0][dt], pa[0], b0, b1);
                mma_tf32(oacc[1][dt], pa[1], b0, b1);
            }
        }
    }

    // ---- normalize + write out [B, S, H*D] ----
    #pragma unroll
    for (int mt = 0; mt < 2; mt++) {
        float inv0 = 1.0f / lrow[mt][0];
        float inv1 = 1.0f / lrow[mt][1];
        int r0 = q0 + wm + mt * 16 + g;
        int r1 = r0 + 8;
        #pragma unroll
        for (int dt = 0; dt < 8; dt++) {
            int d = dt * 8 + 2 * t4;
            float2 v0 = make_float2(oacc[mt][dt][0] * inv0, oacc[mt][dt][1] * inv0);
            float2 v1 = make_float2(oacc[mt][dt][2] * inv1, oacc[mt][dt][3] * inv1);
            *(float2*)&out[(b * SS + r0) * HIDN + h * HD + d] = v0;
            *(float2*)&out[(b * SS + r1) * HIDN + h * HD + d] = v1;
        }
    }
}

// ---------------------------------------------------------------------------
extern "C" void kernel_launch(void* const* d_in, const int* in_sizes, int n_in,
                              void* d_out, int out_size) {
    const float* hs   = (const float*)d_in[0];
    const float* mask = (const float*)d_in[1];
    const float* Wq   = (const float*)d_in[2];
    const float* bq   = (const float*)d_in[3];
    const float* Wk   = (const float*)d_in[4];
    const float* bk   = (const float*)d_in[5];
    const float* Wv   = (const float*)d_in[6];
    const float* bv   = (const float*)d_in[7];
    float* out = (float*)d_out;

    static bool attr_set = false;
    if (!attr_set) {
        cudaFuncSetAttribute(attn_tf32,
                             cudaFuncAttributeMaxDynamicSharedMemorySize,
                             ATTN_SMEM_BYTES);
        cudaFuncSetAttribute(qkv_gemm_tf32,
                             cudaFuncAttributeMaxDynamicSharedMemorySize,
                             QKV_SMEM_BYTES);
        attr_set = true;
    }

    sincos_kernel<<<(SS * 32 + 255) / 256, 256>>>();
    prep_tf32<<<(NX4 + 3 * NW4) / 256, 256>>>((const float4*)hs,
                                              (const float4*)Wq,
                                              (const float4*)Wk,
                                              (const float4*)Wv);
    qkv_gemm_tf32<<<dim3(30, 32), 256, QKV_SMEM_BYTES>>>(bq, bk, bv);
    rope_kernel<<<(BB * NH * SS * 32) / 256, 256>>>();
    attn_tf32<<<dim3(SS / 128, BB * NH), 128, ATTN_SMEM_BYTES>>>(mask, out);
}

// round 9
// speedup vs baseline: 1.0085x; 1.0085x over previous
#include <cuda_runtime.h>
#include <cstdint>
#include <math.h>

#define BB 2
#define SS 2048
#define HIDN 1280
#define NH 20
#define HD 64

// Scratch (alloc-free rule: __device__ globals)
__device__ float g_Q[BB*NH*SS*HD];
__device__ float g_K[BB*NH*SS*HD];
__device__ float g_V[BB*NH*SS*HD];
__device__ float g_Kf[BB*NH*SS*HD];    // K in per-lane mma-fragment order
__device__ float g_Vf[BB*NH*SS*HD];    // V in per-lane mma-fragment order
__device__ float g_X[BB*SS*HIDN];      // tf32-rounded hidden states
__device__ float g_W[3*HIDN*HIDN];     // tf32-rounded Wq|Wk|Wv
__device__ float g_cos[SS*32];
__device__ float g_sin[SS*32];

// ---------------------------------------------------------------------------
// RoPE cos/sin table
// ---------------------------------------------------------------------------
__global__ void sincos_kernel() {
    int idx = blockIdx.x * blockDim.x + threadIdx.x;
    if (idx >= SS * 32) return;
    int j = idx & 31;
    int s = idx >> 5;
    double invf = exp(-((double)j / 32.0) * log(10000.0));
    double a = (double)s * invf;
    g_cos[idx] = (float)cos(a);
    g_sin[idx] = (float)sin(a);
}

// ---------------------------------------------------------------------------
// tf32 helpers
// ---------------------------------------------------------------------------
__device__ __forceinline__ float to_tf32(float x) {
    float r;
    asm("cvt.rna.tf32.f32 %0, %1;" : "=f"(r) : "f"(x));
    return r;
}

__device__ __forceinline__ void mma_tf32(float c[4], const float a[4],
                                         float b0, float b1) {
    asm volatile(
        "mma.sync.aligned.m16n8k8.row.col.f32.tf32.tf32.f32 "
        "{%0,%1,%2,%3}, {%4,%5,%6,%7}, {%8,%9}, {%0,%1,%2,%3};"
        : "+f"(c[0]), "+f"(c[1]), "+f"(c[2]), "+f"(c[3])
        : "r"(__float_as_uint(a[0])), "r"(__float_as_uint(a[1])),
          "r"(__float_as_uint(a[2])), "r"(__float_as_uint(a[3])),
          "r"(__float_as_uint(b0)),  "r"(__float_as_uint(b1)));
}

__device__ __forceinline__ void cp16(unsigned int dst, const void* src) {
    asm volatile("cp.async.cg.shared.global [%0], [%1], 16;\n"
                 :: "r"(dst), "l"(src));
}
__device__ __forceinline__ void cp_commit() {
    asm volatile("cp.async.commit_group;\n" ::: "memory");
}
template <int N>
__device__ __forceinline__ void cp_wait() {
    asm volatile("cp.async.wait_group %0;\n" :: "n"(N) : "memory");
}

// ---------------------------------------------------------------------------
// Prep: round X and the 3 weight matrices to tf32 (rna) into scratch.
// ---------------------------------------------------------------------------
#define NX4 (BB*SS*HIDN/4)
#define NW4 (HIDN*HIDN/4)

__global__ __launch_bounds__(256) void prep_tf32(
    const float4* __restrict__ X,
    const float4* __restrict__ Wq,
    const float4* __restrict__ Wk,
    const float4* __restrict__ Wv)
{
    int i = blockIdx.x * blockDim.x + threadIdx.x;
    float4 v;
    float4* dst;
    if (i < NX4) {
        v = X[i]; dst = ((float4*)g_X) + i;
    } else if (i < NX4 + NW4) {
        int j = i - NX4; v = Wq[j]; dst = ((float4*)g_W) + j;
    } else if (i < NX4 + 2 * NW4) {
        int j = i - NX4 - NW4; v = Wk[j]; dst = ((float4*)g_W) + NW4 + j;
    } else {
        int j = i - NX4 - 2 * NW4; v = Wv[j]; dst = ((float4*)g_W) + 2 * NW4 + j;
    }
    v.x = to_tf32(v.x); v.y = to_tf32(v.y);
    v.z = to_tf32(v.z); v.w = to_tf32(v.w);
    *dst = v;
}

// ---------------------------------------------------------------------------
// Fused QKV projection GEMM — tf32 mma + cp.async 2-stage pipeline (as R7).
// ---------------------------------------------------------------------------
#define QAS 4608
#define QBS 4352
#define QKV_SMEM_BYTES (17920 * 4)

__global__ __launch_bounds__(256, 2) void qkv_gemm_tf32(
    const float* __restrict__ bq,
    const float* __restrict__ bk,
    const float* __restrict__ bv)
{
    extern __shared__ float sm[];

    const int n0g   = blockIdx.x * 128;
    const int m0    = blockIdx.y * 128;
    const int which = n0g / HIDN;
    const int ncol0 = n0g % HIDN;

    const float* Wp   = g_W + (size_t)which * HIDN * HIDN;
    const float* bias = (which == 0) ? bq : (which == 1 ? bk : bv);
    float*       Out  = (which == 0) ? g_Q : (which == 1 ? g_K : g_V);

    const int tid  = threadIdx.x;
    const int lane = tid & 31;
    const int warp = tid >> 5;
    const int wm   = (warp & 1) * 64;
    const int wn   = (warp >> 1) * 32;
    const int g    = lane >> 2;
    const int t4   = lane & 3;

    const unsigned int sbase = (unsigned int)__cvta_generic_to_shared(sm);
    const int a_r  = tid >> 3;
    const int a_k  = (tid & 7) * 4;
    const int b_n  = lane * 4;

    float acc[4][4][4];
    #pragma unroll
    for (int mt = 0; mt < 4; mt++)
        #pragma unroll
        for (int nt = 0; nt < 4; nt++)
            #pragma unroll
            for (int i = 0; i < 4; i++) acc[mt][nt][i] = 0.0f;

    {
        #pragma unroll
        for (int p = 0; p < 4; p++) {
            int r = a_r + 32 * p;
            cp16(sbase + (r * 36 + a_k) * 4, g_X + (m0 + r) * HIDN + a_k);
        }
        #pragma unroll
        for (int p = 0; p < 4; p++) {
            int kk = warp + 8 * p;
            cp16(sbase + (9216 + kk * 136 + b_n) * 4, Wp + kk * HIDN + ncol0 + b_n);
        }
        cp_commit();
    }

    for (int kt = 0; kt < HIDN / 32; kt++) {
        const int buf = kt & 1;
        cp_wait<0>();
        __syncthreads();

        if (kt < HIDN / 32 - 1) {
            const int k0 = (kt + 1) * 32;
            const int ao = (buf ^ 1) * QAS;
            const int bo = 9216 + (buf ^ 1) * QBS;
            #pragma unroll
            for (int p = 0; p < 4; p++) {
                int r = a_r + 32 * p;
                cp16(sbase + (ao + r * 36 + a_k) * 4,
                     g_X + (m0 + r) * HIDN + k0 + a_k);
            }
            #pragma unroll
            for (int p = 0; p < 4; p++) {
                int kk = warp + 8 * p;
                cp16(sbase + (bo + kk * 136 + b_n) * 4,
                     Wp + (k0 + kk) * HIDN + ncol0 + b_n);
            }
            cp_commit();
        }

        const float* A  = sm + buf * QAS;
        const float* Bt = sm + 9216 + buf * QBS;

        #pragma unroll
        for (int kc = 0; kc < 4; kc++) {
            const int kr = kc * 8;
            float a[4][4];
            #pragma unroll
            for (int mt = 0; mt < 4; mt++) {
                int mr = wm + mt * 16;
                a[mt][0] = A[(mr + g    ) * 36 + kr + t4    ];
                a[mt][1] = A[(mr + g + 8) * 36 + kr + t4    ];
                a[mt][2] = A[(mr + g    ) * 36 + kr + t4 + 4];
                a[mt][3] = A[(mr + g + 8) * 36 + kr + t4 + 4];
            }
            #pragma unroll
            for (int nt = 0; nt < 4; nt++) {
                float b0 = Bt[(kr + t4    ) * 136 + wn + nt * 8 + g];
                float b1 = Bt[(kr + t4 + 4) * 136 + wn + nt * 8 + g];
                #pragma unroll
                for (int mt = 0; mt < 4; mt++)
                    mma_tf32(acc[mt][nt], a[mt], b0, b1);
            }
        }
    }

    #pragma unroll
    for (int mt = 0; mt < 4; mt++) {
        #pragma unroll
        for (int nt = 0; nt < 4; nt++) {
            int col = ncol0 + wn + nt * 8 + t4 * 2;
            int h = col >> 6;
            int d = col & 63;
            float bi0 = bias[col];
            float bi1 = bias[col + 1];
            #pragma unroll
            for (int rh = 0; rh < 2; rh++) {
                int m = m0 + wm + mt * 16 + g + rh * 8;
                int b = m >> 11;
                int s = m & 2047;
                float2 v;
                v.x = acc[mt][nt][rh * 2 + 0] + bi0;
                v.y = acc[mt][nt][rh * 2 + 1] + bi1;
                *(float2*)&Out[(((b * NH + h) * SS) + s) * HD + d] = v;
            }
        }
    }
}

// ---------------------------------------------------------------------------
// RoPE (+ query scaling). Pre-rounds Q, K, V to tf32.
// ---------------------------------------------------------------------------
__global__ __launch_bounds__(256) void rope_kernel() {
    int idx = blockIdx.x * blockDim.x + threadIdx.x;
    int j  = idx & 31;
    int s  = (idx >> 5) & (SS - 1);
    int bh = idx >> 16;
    float c  = g_cos[(s << 5) + j];
    float sn = g_sin[(s << 5) + j];
    int base = (bh * SS + s) * HD;
    const float scale = 0.125f;

    float q1 = g_Q[base + j], q2 = g_Q[base + j + 32];
    g_Q[base + j]      = to_tf32((q1 * c - q2 * sn) * scale);
    g_Q[base + j + 32] = to_tf32((q2 * c + q1 * sn) * scale);

    float k1 = g_K[base + j], k2 = g_K[base + j + 32];
    g_K[base + j]      = to_tf32(k1 * c - k2 * sn);
    g_K[base + j + 32] = to_tf32(k2 * c + k1 * sn);

    g_V[base + j]      = to_tf32(g_V[base + j]);
    g_V[base + j + 32] = to_tf32(g_V[base + j + 32]);
}

// ---------------------------------------------------------------------------
// Repack K and V into per-lane mma B-fragment order (once per tile).
// g_Kf[((bh*64 + tile)*32 + lane)*64 + v]:
//   K: v = nt*16 + u  -> K[tile*32 + nt*8 + (lane>>2)][(lane&3) + 4u]
//   V: v = kc*16 + dt*2 + s -> V[tile*32 + 8kc + (lane&3) + 4s][dt*8 + (lane>>2)]
// Consumer reads lane-contiguous 16B chunks -> LDS.128 fragments.
// ---------------------------------------------------------------------------
__global__ __launch_bounds__(256) void repack_kv() {
    __shared__ float Ks[32][68];
    __shared__ float Vs[32][68];

    const int tile = blockIdx.x;          // 0..63
    const int bh   = blockIdx.y;          // 0..39
    const float* Kb = g_K + ((size_t)bh * SS + tile * 32) * HD;
    const float* Vb = g_V + ((size_t)bh * SS + tile * 32) * HD;

    const int t = threadIdx.x;
    const int r0 = t >> 4;                // 0..15
    const int c0 = (t & 15) * 4;          // 0..60

    #pragma unroll
    for (int p = 0; p < 2; p++) {
        int r = r0 + 16 * p;
        *(float4*)&Ks[r][c0] = *(const float4*)&Kb[r * HD + c0];
        *(float4*)&Vs[r][c0] = *(const float4*)&Vb[r * HD + c0];
    }
    __syncthreads();

    const int lane = t >> 3;              // 0..31
    const int q    = t & 7;               // 0..7 (8 vals per thread)
    const int g    = lane >> 2;
    const int t4   = lane & 3;
    const size_t obase = (((size_t)bh * 64 + tile) * 32 + lane) * 64 + q * 8;

    float ok[8], ov[8];
    #pragma unroll
    for (int i = 0; i < 8; i++) {
        int v  = q * 8 + i;
        int nt = v >> 4, u = v & 15;
        ok[i] = Ks[nt * 8 + g][t4 + 4 * u];
        int kc = v >> 4, rem = v & 15, dt = rem >> 1, s = rem & 1;
        ov[i] = Vs[8 * kc + t4 + 4 * s][dt * 8 + g];
    }
    *(float4*)&g_Kf[obase]     = *(float4*)&ok[0];
    *(float4*)&g_Kf[obase + 4] = *(float4*)&ok[4];
    *(float4*)&g_Vf[obase]     = *(float4*)&ov[0];
    *(float4*)&g_Vf[obase + 4] = *(float4*)&ov[4];
}

// ---------------------------------------------------------------------------
// Flash attention, tf32 mma, cp.async double-buffered K/V in FRAGMENT layout.
// BQ=64, 4 warps (m16 each), BKV=32. K/V fragments read via LDS.128.
// Dynamic smem (floats):
//   [0,    4352)  Qs[64][68] staging, reused as Ps[64][36]
//   [4352, 6528)  K buf0 [32 lanes][68]
//   [6528, 8704)  K buf1
//   [8704,10880)  V buf0 [32 lanes][68]
//   [10880,13056) V buf1
// ---------------------------------------------------------------------------
#define OFF_K0 4352
#define OFF_V0 8704
#define FBUF 2176
#define ATTN_SMEM_BYTES (13056 * 4)

__global__ __launch_bounds__(128) void attn_tf32(
    const float* __restrict__ mask, float* __restrict__ out)
{
    extern __shared__ float sm[];
    float (*Ps)[36] = (float(*)[36])sm;

    const int bh = blockIdx.y;
    const int b  = bh / NH;
    const int h  = bh % NH;
    const int q0 = blockIdx.x * 64;

    const float* Qb  = g_Q  + (size_t)bh * SS * HD;
    const float* Kfb = g_Kf + (size_t)bh * SS * HD;   // 64 tiles * 2048 floats
    const float* Vfb = g_Vf + (size_t)bh * SS * HD;
    const float2* mk2 = (const float2*)(mask + b * SS);

    const int tid  = threadIdx.x;
    const int lane = tid & 31;
    const int warp = tid >> 5;
    const int g    = lane >> 2;
    const int t4   = lane & 3;
    const int wm   = warp * 16;

    const unsigned int sbase = (unsigned int)__cvta_generic_to_shared(sm);
    const int c_lane = tid >> 2;          // 0..31 target lane block
    const int c_off  = (tid & 3) * 4;     // float offset (+16p covers 64)

    // Prologue: issue tile 0 fragment copies into buffer 0
    {
        #pragma unroll
        for (int p = 0; p < 4; p++) {
            int o = c_off + 16 * p;
            cp16(sbase + (OFF_K0 + c_lane * 68 + o) * 4, Kfb + c_lane * 64 + o);
            cp16(sbase + (OFF_V0 + c_lane * 68 + o) * 4, Vfb + c_lane * 64 + o);
        }
        cp_commit();
    }

    // Stage Q (64 x 64, already tf32-rounded)
    for (int i = tid; i < 1024; i += 128) {
        int r = i >> 4, c = (i & 15) << 2;
        *(float4*)&sm[r * 68 + c] = *(const float4*)&Qb[(q0 + r) * HD + c];
    }
    __syncthreads();

    // Hoist Q fragments
    float qf[8][4];
    #pragma unroll
    for (int kc = 0; kc < 8; kc++) {
        int kr = kc * 8;
        qf[kc][0] = sm[(wm + g    ) * 68 + kr + t4    ];
        qf[kc][1] = sm[(wm + g + 8) * 68 + kr + t4    ];
        qf[kc][2] = sm[(wm + g    ) * 68 + kr + t4 + 4];
        qf[kc][3] = sm[(wm + g + 8) * 68 + kr + t4 + 4];
    }

    float oacc[8][4];
    #pragma unroll
    for (int dt = 0; dt < 8; dt++)
        #pragma unroll
        for (int i = 0; i < 4; i++) oacc[dt][i] = 0.0f;
    float m0r = -1e30f, m1r = -1e30f, l0 = 0.0f, l1 = 0.0f;

    for (int it = 0; it < SS / 32; it++) {
        const int buf = it & 1;
        cp_wait<0>();
        __syncthreads();   // buf visible + everyone done reading buf^1

        if (it < SS / 32 - 1) {
            const float* Kn = Kfb + (it + 1) * 2048;
            const float* Vn = Vfb + (it + 1) * 2048;
            int ko = OFF_K0 + (buf ^ 1) * FBUF;
            int vo = OFF_V0 + (buf ^ 1) * FBUF;
            #pragma unroll
            for (int p = 0; p < 4; p++) {
                int o = c_off + 16 * p;
                cp16(sbase + (ko + c_lane * 68 + o) * 4, Kn + c_lane * 64 + o);
                cp16(sbase + (vo + c_lane * 68 + o) * 4, Vn + c_lane * 64 + o);
            }
            cp_commit();
        }

        const float4* K4 = (const float4*)(sm + OFF_K0 + buf * FBUF);
        const float4* V4 = (const float4*)(sm + OFF_V0 + buf * FBUF);
        const int lb = lane * 17;   // 68 floats = 17 float4 per lane

        // ---- S = Q @ K^T (m16 x n32); K frags via LDS.128 ----
        float sc[4][4];
        #pragma unroll
        for (int nt = 0; nt < 4; nt++)
            #pragma unroll
            for (int i = 0; i < 4; i++) sc[nt][i] = 0.0f;

        #pragma unroll
        for (int nt = 0; nt < 4; nt++) {
            float kf[16];
            #pragma unroll
            for (int w = 0; w < 4; w++)
                *(float4*)&kf[w * 4] = K4[lb + nt * 4 + w];
            #pragma unroll
            for (int kc = 0; kc < 8; kc++)
                mma_tf32(sc[nt], qf[kc], kf[2 * kc], kf[2 * kc + 1]);
        }

        // ---- mask + online softmax ----
        const int k0 = it * 32;
        #pragma unroll
        for (int nt = 0; nt < 4; nt++) {
            float2 mv = __ldg(&mk2[(k0 + nt * 8) / 2 + t4]);
            sc[nt][0] += mv.x; sc[nt][1] += mv.y;
            sc[nt][2] += mv.x; sc[nt][3] += mv.y;
        }
        float rx0 = -1e30f, rx1 = -1e30f;
        #pragma unroll
        for (int nt = 0; nt < 4; nt++) {
            rx0 = fmaxf(rx0, fmaxf(sc[nt][0], sc[nt][1]));
            rx1 = fmaxf(rx1, fmaxf(sc[nt][2], sc[nt][3]));
        }
        rx0 = fmaxf(rx0, __shfl_xor_sync(0xffffffffu, rx0, 1));
        rx0 = fmaxf(rx0, __shfl_xor_sync(0xffffffffu, rx0, 2));
        rx1 = fmaxf(rx1, __shfl_xor_sync(0xffffffffu, rx1, 1));
        rx1 = fmaxf(rx1, __shfl_xor_sync(0xffffffffu, rx1, 2));

        float m0n = fmaxf(m0r, rx0);
        float m1n = fmaxf(m1r, rx1);
        float c0 = __expf(m0r - m0n);
        float c1 = __expf(m1r - m1n);
        m0r = m0n; m1r = m1n;

        float rs0 = 0.0f, rs1 = 0.0f;
        #pragma unroll
        for (int nt = 0; nt < 4; nt++) {
            float p0 = to_tf32(__expf(sc[nt][0] - m0n));
            float p1 = to_tf32(__expf(sc[nt][1] - m0n));
            float p2 = to_tf32(__expf(sc[nt][2] - m1n));
            float p3 = to_tf32(__expf(sc[nt][3] - m1n));
            rs0 += p0 + p1;
            rs1 += p2 + p3;
            *(float2*)&Ps[wm + g    ][nt * 8 + 2 * t4] = make_float2(p0, p1);
            *(float2*)&Ps[wm + g + 8][nt * 8 + 2 * t4] = make_float2(p2, p3);
        }
        rs0 += __shfl_xor_sync(0xffffffffu, rs0, 1);
        rs0 += __shfl_xor_sync(0xffffffffu, rs0, 2);
        rs1 += __shfl_xor_sync(0xffffffffu, rs1, 1);
        rs1 += __shfl_xor_sync(0xffffffffu, rs1, 2);
        l0 = l0 * c0 + rs0;
        l1 = l1 * c1 + rs1;

        #pragma unroll
        for (int dt = 0; dt < 8; dt++) {
            oacc[dt][0] *= c0; oacc[dt][1] *= c0;
            oacc[dt][2] *= c1; oacc[dt][3] *= c1;
        }
        __syncwarp();   // Ps rows are warp-private

        // ---- O += P @ V (m16 x n64, k32); V frags via LDS.128 ----
        #pragma unroll
        for (int kc = 0; kc < 4; kc++) {
            int kr = kc * 8;
            float pa[4];
            pa[0] = Ps[wm + g    ][kr + t4    ];
            pa[1] = Ps[wm + g + 8][kr + t4    ];
            pa[2] = Ps[wm + g    ][kr + t4 + 4];
            pa[3] = Ps[wm + g + 8][kr + t4 + 4];
            float vf[16];
            #pragma unroll
            for (int w = 0; w < 4; w++)
                *(float4*)&vf[w * 4] = V4[lb + kc * 4 + w];
            #pragma unroll
            for (int dt = 0; dt < 8; dt++)
                mma_tf32(oacc[dt], pa, vf[2 * dt], vf[2 * dt + 1]);
        }
    }

    // ---- normalize + write out [B, S, H*D] ----
    float inv0 = 1.0f / l0;
    float inv1 = 1.0f / l1;
    int r0 = q0 + wm + g;
    int r1 = r0 + 8;
    #pragma unroll
    for (int dt = 0; dt < 8; dt++) {
        int d = dt * 8 + 2 * t4;
        float2 v0 = make_float2(oacc[dt][0] * inv0, oacc[dt][1] * inv0);
        float2 v1 = make_float2(oacc[dt][2] * inv1, oacc[dt][3] * inv1);
        *(float2*)&out[(b * SS + r0) * HIDN + h * HD + d] = v0;
        *(float2*)&out[(b * SS + r1) * HIDN + h * HD + d] = v1;
    }
}

// ---------------------------------------------------------------------------
extern "C" void kernel_launch(void* const* d_in, const int* in_sizes, int n_in,
                              void* d_out, int out_size) {
    const float* hs   = (const float*)d_in[0];
    const float* mask = (const float*)d_in[1];
    const float* Wq   = (const float*)d_in[2];
    const float* bq   = (const float*)d_in[3];
    const float* Wk   = (const float*)d_in[4];
    const float* bk   = (const float*)d_in[5];
    const float* Wv   = (const float*)d_in[6];
    const float* bv   = (const float*)d_in[7];
    float* out = (float*)d_out;

    static bool attr_set = false;
    if (!attr_set) {
        cudaFuncSetAttribute(attn_tf32,
                             cudaFuncAttributeMaxDynamicSharedMemorySize,
                             ATTN_SMEM_BYTES);
        cudaFuncSetAttribute(qkv_gemm_tf32,
                             cudaFuncAttributeMaxDynamicSharedMemorySize,
                             QKV_SMEM_BYTES);
        attr_set = true;
    }

    sincos_kernel<<<(SS * 32 + 255) / 256, 256>>>();
    prep_tf32<<<(NX4 + 3 * NW4) / 256, 256>>>((const float4*)hs,
                                              (const float4*)Wq,
                                              (const float4*)Wk,
                                              (const float4*)Wv);
    qkv_gemm_tf32<<<dim3(30, 32), 256, QKV_SMEM_BYTES>>>(bq, bk, bv);
    rope_kernel<<<(BB * NH * SS * 32) / 256, 256>>>();
    repack_kv<<<dim3(SS / 32, BB * NH), 256>>>();
    attn_tf32<<<dim3(SS / 64, BB * NH), 128, ATTN_SMEM_BYTES>>>(mask, out);
}

// round 11
// speedup vs baseline: 1.3756x; 1.3640x over previous
#include <cuda_runtime.h>
#include <cuda_fp16.h>
#include <cstdint>
#include <math.h>

#define BB 2
#define SS 2048
#define HIDN 1280
#define NH 20
#define HD 64

// Scratch (alloc-free rule: __device__ globals)
__device__ float g_Q[BB*NH*SS*HD];
__device__ float g_K[BB*NH*SS*HD];
__device__ float g_V[BB*NH*SS*HD];
__device__ unsigned g_Qh[BB*NH*SS*HD/2];     // Q fp16 (half2-packed along d)
__device__ unsigned g_Kf[BB*NH*SS*HD/2];     // K fp16, per-lane mma B-frag order
__device__ unsigned g_Vf[BB*NH*SS*HD/2];     // V fp16, per-lane mma B-frag order
__device__ unsigned g_Xh[BB*SS*HIDN/2];      // hidden states fp16
__device__ unsigned g_Wth[3*HIDN*HIDN/2];    // transposed weights fp16 ([n][k])
__device__ float g_cos[SS*32];
__device__ float g_sin[SS*32];

// ---------------------------------------------------------------------------
// helpers
// ---------------------------------------------------------------------------
__device__ __forceinline__ unsigned packh2(float x, float y) {
    __half2 h = __floats2half2_rn(x, y);
    return *reinterpret_cast<unsigned*>(&h);
}

__device__ __forceinline__ void mma_f16(float c[4], const unsigned a[4],
                                        unsigned b0, unsigned b1) {
    asm volatile(
        "mma.sync.aligned.m16n8k16.row.col.f32.f16.f16.f32 "
        "{%0,%1,%2,%3}, {%4,%5,%6,%7}, {%8,%9}, {%0,%1,%2,%3};"
        : "+f"(c[0]), "+f"(c[1]), "+f"(c[2]), "+f"(c[3])
        : "r"(a[0]), "r"(a[1]), "r"(a[2]), "r"(a[3]),
          "r"(b0), "r"(b1));
}

__device__ __forceinline__ void cp16(unsigned int dst, const void* src) {
    asm volatile("cp.async.cg.shared.global [%0], [%1], 16;\n"
                 :: "r"(dst), "l"(src));
}
__device__ __forceinline__ void cp_commit() {
    asm volatile("cp.async.commit_group;\n" ::: "memory");
}
template <int N>
__device__ __forceinline__ void cp_wait() {
    asm volatile("cp.async.wait_group %0;\n" :: "n"(N) : "memory");
}

// ---------------------------------------------------------------------------
// RoPE cos/sin table
// ---------------------------------------------------------------------------
__global__ void sincos_kernel() {
    int idx = blockIdx.x * blockDim.x + threadIdx.x;
    if (idx >= SS * 32) return;
    int j = idx & 31;
    int s = idx >> 5;
    double invf = exp(-((double)j / 32.0) * log(10000.0));
    double a = (double)s * invf;
    g_cos[idx] = (float)cos(a);
    g_sin[idx] = (float)sin(a);
}

// ---------------------------------------------------------------------------
// Convert hidden states to fp16 (half2-packed)
// ---------------------------------------------------------------------------
__global__ __launch_bounds__(256) void round_xh(const float4* __restrict__ X) {
    int i = blockIdx.x * blockDim.x + threadIdx.x;   // uint4 index
    float4 a = X[2 * i], b = X[2 * i + 1];
    uint4 o;
    o.x = packh2(a.x, a.y);
    o.y = packh2(a.z, a.w);
    o.z = packh2(b.x, b.y);
    o.w = packh2(b.z, b.w);
    ((uint4*)g_Xh)[i] = o;
}

// ---------------------------------------------------------------------------
// Transpose + fp16-pack the three weight matrices: g_Wth[which][n][k]=W[k][n]
// ---------------------------------------------------------------------------
__global__ __launch_bounds__(256) void wt_transpose_h(
    const float* __restrict__ Wq,
    const float* __restrict__ Wk,
    const float* __restrict__ Wv)
{
    __shared__ float t[32][33];
    const float* W = (blockIdx.z == 0) ? Wq : (blockIdx.z == 1 ? Wk : Wv);
    unsigned* Out = g_Wth + (size_t)blockIdx.z * (HIDN * HIDN / 2);
    int k0 = blockIdx.x * 32, n0 = blockIdx.y * 32;
    int tx = threadIdx.x & 31, ty = threadIdx.x >> 5;   // 32 x 8
    #pragma unroll
    for (int p = 0; p < 4; p++) {
        int k = ty + p * 8;
        t[k][tx] = W[(k0 + k) * HIDN + n0 + tx];
    }
    __syncthreads();
    int nb = threadIdx.x >> 4;      // 0..15
    int kp = threadIdx.x & 15;      // k-pair 0..15
    #pragma unroll
    for (int p = 0; p < 2; p++) {
        int n = nb + p * 16;
        Out[(size_t)(n0 + n) * (HIDN / 2) + k0 / 2 + kp] =
            packh2(t[2 * kp][n], t[2 * kp + 1][n]);
    }
}

// ---------------------------------------------------------------------------
// Fused QKV projection GEMM — fp16 mma.m16n8k16 + cp.async 2-stage pipeline.
// Block tile 128x128, 8 warps (2m x 4n), warp tile 64x32.
// K chunk = 64 halves (32 uint32/row), 20 chunks.
// Dynamic smem (uint32): A0 [0,4608) A1 [4608,9216) B0 [9216,13824) B1 [13824,18432)
// Row stride 36 uint32 (conflict-free: banks 4g+t4+8s).
// ---------------------------------------------------------------------------
#define QKV_SMEM_BYTES (18432 * 4)

__global__ __launch_bounds__(256, 2) void qkv_gemm_fp16(
    const float* __restrict__ bq,
    const float* __restrict__ bk,
    const float* __restrict__ bv)
{
    extern __shared__ unsigned smu[];

    const int n0g   = blockIdx.x * 128;
    const int m0    = blockIdx.y * 128;
    const int which = n0g / HIDN;
    const int ncol0 = n0g % HIDN;

    const unsigned* Wp = g_Wth + (size_t)which * (HIDN * HIDN / 2);
    const float* bias  = (which == 0) ? bq : (which == 1 ? bk : bv);
    float*       Out   = (which == 0) ? g_Q : (which == 1 ? g_K : g_V);

    const int tid  = threadIdx.x;
    const int lane = tid & 31;
    const int warp = tid >> 5;
    const int wm   = (warp & 1) * 64;
    const int wn   = (warp >> 1) * 32;
    const int g    = lane >> 2;
    const int t4   = lane & 3;

    const unsigned int sbase = (unsigned int)__cvta_generic_to_shared(smu);
    const int st_row = tid & 127;        // staged row
    const int st_seg = tid >> 7;         // 0/1: which 16-uint32 half of row

    float acc[4][4][4];
    #pragma unroll
    for (int mt = 0; mt < 4; mt++)
        #pragma unroll
        for (int nt = 0; nt < 4; nt++)
            #pragma unroll
            for (int i = 0; i < 4; i++) acc[mt][nt][i] = 0.0f;

    const unsigned* srcA = g_Xh + (size_t)(m0 + st_row) * (HIDN / 2);
    const unsigned* srcB = Wp + (size_t)(ncol0 + st_row) * (HIDN / 2);

    // Prologue: stage chunk 0 into buffer 0
    {
        #pragma unroll
        for (int u = 0; u < 4; u++) {
            int o = st_seg * 16 + u * 4;
            cp16(sbase + (st_row * 36 + o) * 4, srcA + o);
            cp16(sbase + (9216 + st_row * 36 + o) * 4, srcB + o);
        }
        cp_commit();
    }

    for (int kt = 0; kt < 20; kt++) {
        const int buf = kt & 1;
        cp_wait<0>();
        __syncthreads();   // chunk kt visible + all done reading buf^1

        if (kt < 19) {
            const int k32 = (kt + 1) * 32;   // uint32 offset of next chunk
            const int ao = (buf ^ 1) * 4608;
            const int bo = 9216 + (buf ^ 1) * 4608;
            #pragma unroll
            for (int u = 0; u < 4; u++) {
                int o = st_seg * 16 + u * 4;
                cp16(sbase + (ao + st_row * 36 + o) * 4, srcA + k32 + o);
                cp16(sbase + (bo + st_row * 36 + o) * 4, srcB + k32 + o);
            }
            cp_commit();
        }

        const unsigned* A  = smu + buf * 4608;
        const unsigned* Bt = smu + 9216 + buf * 4608;

        #pragma unroll
        for (int s = 0; s < 4; s++) {        // 4 k16 steps per 64-half chunk
            const int ko = s * 8;
            unsigned a[4][4];
            #pragma unroll
            for (int mt = 0; mt < 4; mt++) {
                int mr = wm + mt * 16;
                a[mt][0] = A[(mr + g    ) * 36 + ko + t4    ];
                a[mt][1] = A[(mr + g + 8) * 36 + ko + t4    ];
                a[mt][2] = A[(mr + g    ) * 36 + ko + t4 + 4];
                a[mt][3] = A[(mr + g + 8) * 36 + ko + t4 + 4];
            }
            #pragma unroll
            for (int nt = 0; nt < 4; nt++) {
                int col = wn + nt * 8 + g;
                unsigned b0 = Bt[col * 36 + ko + t4    ];
                unsigned b1 = Bt[col * 36 + ko + t4 + 4];
                #pragma unroll
                for (int mt = 0; mt < 4; mt++)
                    mma_f16(acc[mt][nt], a[mt], b0, b1);
            }
        }
    }

    // Epilogue: bias + scatter into [B, H, S, D] (fp32)
    #pragma unroll
    for (int mt = 0; mt < 4; mt++) {
        #pragma unroll
        for (int nt = 0; nt < 4; nt++) {
            int col = ncol0 + wn + nt * 8 + t4 * 2;
            int h = col >> 6;
            int d = col & 63;
            float bi0 = bias[col];
            float bi1 = bias[col + 1];
            #pragma unroll
            for (int rh = 0; rh < 2; rh++) {
                int m = m0 + wm + mt * 16 + g + rh * 8;
                int b = m >> 11;
                int s = m & 2047;
                float2 v;
                v.x = acc[mt][nt][rh * 2 + 0] + bi0;
                v.y = acc[mt][nt][rh * 2 + 1] + bi1;
                *(float2*)&Out[(((b * NH + h) * SS) + s) * HD + d] = v;
            }
        }
    }
}

// ---------------------------------------------------------------------------
// RoPE: Q -> rotated, scaled, fp16-packed into g_Qh.
//       K -> rotated in place (fp32; repack converts to fp16).
// Thread handles j2 in [0,16): d = 2j2, 2j2+1, 2j2+32, 2j2+33.
// ---------------------------------------------------------------------------
__global__ __launch_bounds__(256) void rope_kernel_h() {
    int idx = blockIdx.x * blockDim.x + threadIdx.x;   // < BB*NH*SS*16
    int j2 = idx & 15;
    int s  = (idx >> 4) & (SS - 1);
    int bh = idx >> 15;
    int j  = 2 * j2;
    float c0 = g_cos[(s << 5) + j],     c1 = g_cos[(s << 5) + j + 1];
    float s0 = g_sin[(s << 5) + j],     s1 = g_sin[(s << 5) + j + 1];
    int base = (bh * SS + s) * HD;
    const float scale = 0.125f;

    float q1x = g_Q[base + j],      q1y = g_Q[base + j + 1];
    float q2x = g_Q[base + j + 32], q2y = g_Q[base + j + 33];
    g_Qh[(base >> 1) + j2]      = packh2((q1x * c0 - q2x * s0) * scale,
                                         (q1y * c1 - q2y * s1) * scale);
    g_Qh[(base >> 1) + 16 + j2] = packh2((q2x * c0 + q1x * s0) * scale,
                                         (q2y * c1 + q1y * s1) * scale);

    float k1x = g_K[base + j],      k1y = g_K[base + j + 1];
    float k2x = g_K[base + j + 32], k2y = g_K[base + j + 33];
    g_K[base + j]      = k1x * c0 - k2x * s0;
    g_K[base + j + 1]  = k1y * c1 - k2y * s1;
    g_K[base + j + 32] = k2x * c0 + k1x * s0;
    g_K[base + j + 33] = k2y * c1 + k1y * s1;
}

// ---------------------------------------------------------------------------
// Repack K and V (fp32) into fp16 per-lane mma B-fragment order.
// Per lane: 32 uint32 K + 32 uint32 V per 32-key tile.
//   K: vi = nt*8 + kc*2 + b -> half2 K[nt*8+g][2t4+16kc+8b .. +1]
//   V: vi = dt*4 + s*2 + b  -> half2 (V[k0][dt*8+g], V[k0+1][dt*8+g]),
//      k0 = 2t4 + 16s + 8b
// ---------------------------------------------------------------------------
__global__ __launch_bounds__(256) void repack_kvh() {
    __shared__ float Ks[32][68];
    __shared__ float Vs[32][68];

    const int tile = blockIdx.x;
    const int bh   = blockIdx.y;
    const float* Kb = g_K + ((size_t)bh * SS + tile * 32) * HD;
    const float* Vb = g_V + ((size_t)bh * SS + tile * 32) * HD;

    const int t = threadIdx.x;
    const int r0 = t >> 4;
    const int c0 = (t & 15) * 4;

    #pragma unroll
    for (int p = 0; p < 2; p++) {
        int r = r0 + 16 * p;
        *(float4*)&Ks[r][c0] = *(const float4*)&Kb[r * HD + c0];
        *(float4*)&Vs[r][c0] = *(const float4*)&Vb[r * HD + c0];
    }
    __syncthreads();

    const int lane = t >> 3;
    const int q    = t & 7;             // handles vi = 4q .. 4q+3
    const int g    = lane >> 2;
    const int t4   = lane & 3;
    const size_t rowidx = ((size_t)bh * 64 + tile) * 32 + lane;

    unsigned ok[4], ov[4];
    #pragma unroll
    for (int i = 0; i < 4; i++) {
        int vi = q * 4 + i;
        int nt = vi >> 3, r = vi & 7, kc = r >> 1, b = r & 1;
        int d0 = 2 * t4 + 16 * kc + 8 * b;
        ok[i] = packh2(Ks[nt * 8 + g][d0], Ks[nt * 8 + g][d0 + 1]);
        int dt = vi >> 2, r2 = vi & 3, sx = r2 >> 1, bv = r2 & 1;
        int k0 = 2 * t4 + 16 * sx + 8 * bv;
        ov[i] = packh2(Vs[k0][dt * 8 + g], Vs[k0 + 1][dt * 8 + g]);
    }
    ((uint4*)g_Kf)[rowidx * 8 + q] = *(uint4*)&ok[0];
    ((uint4*)g_Vf)[rowidx * 8 + q] = *(uint4*)&ov[0];
}

// ---------------------------------------------------------------------------
// Flash attention, fp16 mma.m16n8k16, cp.async double-buffered fragment K/V.
// BQ=64, 4 warps (m16 each), BKV=32.
// Dynamic smem (uint32):
//   [0,    2304)  Qs2[64][36] staging (data 32/row); overlaid Ps2[64][20]
//   [2304, 3456)  K buf0 [32 lanes][36]
//   [3456, 4608)  K buf1
//   [4608, 5760)  V buf0
//   [5760, 6912)  V buf1
// ---------------------------------------------------------------------------
#define AOFF_K 2304
#define AOFF_V 4608
#define ABUF 1152
#define ATTN_SMEM_BYTES (6912 * 4)

__global__ __launch_bounds__(128) void attn_fp16(
    const float* __restrict__ mask, float* __restrict__ out)
{
    extern __shared__ unsigned smu[];

    const int bh = blockIdx.y;
    const int b  = bh / NH;
    const int h  = bh % NH;
    const int q0 = blockIdx.x * 64;

    const unsigned* Qhb = g_Qh + (size_t)(bh * SS + q0) * 32;
    const unsigned* Kfb = g_Kf + (size_t)bh * 65536;   // 64 tiles * 1024 u32
    const unsigned* Vfb = g_Vf + (size_t)bh * 65536;
    const float2* mk2 = (const float2*)(mask + b * SS);

    const int tid  = threadIdx.x;
    const int lane = tid & 31;
    const int warp = tid >> 5;
    const int g    = lane >> 2;
    const int t4   = lane & 3;
    const int wm   = warp * 16;

    const unsigned int sbase = (unsigned int)__cvta_generic_to_shared(smu);
    const int c_lane = tid >> 2;         // 0..31
    const int c_seg  = tid & 3;          // 0..3: uint32 [8s, 8s+8)

    // Prologue: issue tile 0 K/V fragment copies into buffer 0
    {
        #pragma unroll
        for (int u = 0; u < 2; u++) {
            int o = c_seg * 8 + u * 4;
            cp16(sbase + (AOFF_K + c_lane * 36 + o) * 4, Kfb + c_lane * 32 + o);
            cp16(sbase + (AOFF_V + c_lane * 36 + o) * 4, Vfb + c_lane * 32 + o);
        }
        cp_commit();
    }

    // Stage Q (64 rows x 32 uint32)
    for (int i = tid; i < 512; i += 128) {
        int row = i >> 3, c4 = (i & 7) * 4;
        *(uint4*)&smu[row * 36 + c4] = ((const uint4*)Qhb)[i];
    }
    __syncthreads();

    // Hoist Q fragments (4 k16 steps x 4 regs)
    unsigned qf[4][4];
    #pragma unroll
    for (int kc = 0; kc < 4; kc++) {
        qf[kc][0] = smu[(wm + g    ) * 36 + kc * 8 + t4    ];
        qf[kc][1] = smu[(wm + g + 8) * 36 + kc * 8 + t4    ];
        qf[kc][2] = smu[(wm + g    ) * 36 + kc * 8 + t4 + 4];
        qf[kc][3] = smu[(wm + g + 8) * 36 + kc * 8 + t4 + 4];
    }

    float oacc[8][4];
    #pragma unroll
    for (int dt = 0; dt < 8; dt++)
        #pragma unroll
        for (int i = 0; i < 4; i++) oacc[dt][i] = 0.0f;
    float m0r = -1e30f, m1r = -1e30f, l0 = 0.0f, l1 = 0.0f;

    for (int it = 0; it < SS / 32; it++) {
        const int buf = it & 1;
        cp_wait<0>();
        __syncthreads();   // buf visible + all done reading buf^1

        if (it < SS / 32 - 1) {
            const unsigned* Kn = Kfb + (it + 1) * 1024;
            const unsigned* Vn = Vfb + (it + 1) * 1024;
            int ko = AOFF_K + (buf ^ 1) * ABUF;
            int vo = AOFF_V + (buf ^ 1) * ABUF;
            #pragma unroll
            for (int u = 0; u < 2; u++) {
                int o = c_seg * 8 + u * 4;
                cp16(sbase + (ko + c_lane * 36 + o) * 4, Kn + c_lane * 32 + o);
                cp16(sbase + (vo + c_lane * 36 + o) * 4, Vn + c_lane * 32 + o);
            }
            cp_commit();
        }

        const uint4* K4 = (const uint4*)(smu + AOFF_K + buf * ABUF);
        const uint4* V4 = (const uint4*)(smu + AOFF_V + buf * ABUF);
        const int lb = lane * 9;   // 36 uint32 = 9 uint4 per lane

        // ---- S = Q @ K^T (m16 x n32), fp16 frags via LDS.128 ----
        float sc[4][4];
        #pragma unroll
        for (int nt = 0; nt < 4; nt++)
            #pragma unroll
            for (int i = 0; i < 4; i++) sc[nt][i] = 0.0f;

        #pragma unroll
        for (int nt = 0; nt < 4; nt++) {
            unsigned kf[8];
            *(uint4*)&kf[0] = K4[lb + nt * 2];
            *(uint4*)&kf[4] = K4[lb + nt * 2 + 1];
            #pragma unroll
            for (int kc = 0; kc < 4; kc++)
                mma_f16(sc[nt], qf[kc], kf[kc * 2], kf[kc * 2 + 1]);
        }

        // ---- mask + online softmax ----
        const int k0 = it * 32;
        #pragma unroll
        for (int nt = 0; nt < 4; nt++) {
            float2 mv = __ldg(&mk2[(k0 + nt * 8) / 2 + t4]);
            sc[nt][0] += mv.x; sc[nt][1] += mv.y;
            sc[nt][2] += mv.x; sc[nt][3] += mv.y;
        }
        float rx0 = -1e30f, rx1 = -1e30f;
        #pragma unroll
        for (int nt = 0; nt < 4; nt++) {
            rx0 = fmaxf(rx0, fmaxf(sc[nt][0], sc[nt][1]));
            rx1 = fmaxf(rx1, fmaxf(sc[nt][2], sc[nt][3]));
        }
        rx0 = fmaxf(rx0, __shfl_xor_sync(0xffffffffu, rx0, 1));
        rx0 = fmaxf(rx0, __shfl_xor_sync(0xffffffffu, rx0, 2));
        rx1 = fmaxf(rx1, __shfl_xor_sync(0xffffffffu, rx1, 1));
        rx1 = fmaxf(rx1, __shfl_xor_sync(0xffffffffu, rx1, 2));

        float m0n = fmaxf(m0r, rx0);
        float m1n = fmaxf(m1r, rx1);
        float c0 = __expf(m0r - m0n);
        float c1 = __expf(m1r - m1n);
        m0r = m0n; m1r = m1n;

        // Ps2 overlays Qs2 region: rows stride 20 uint32
        float rs0 = 0.0f, rs1 = 0.0f;
        #pragma unroll
        for (int nt = 0; nt < 4; nt++) {
            float p0 = __expf(sc[nt][0] - m0n);
            float p1 = __expf(sc[nt][1] - m0n);
            float p2 = __expf(sc[nt][2] - m1n);
            float p3 = __expf(sc[nt][3] - m1n);
            unsigned h01 = packh2(p0, p1);
            unsigned h23 = packh2(p2, p3);
            float2 f01 = __half22float2(*(__half2*)&h01);
            float2 f23 = __half22float2(*(__half2*)&h23);
            rs0 += f01.x + f01.y;
            rs1 += f23.x + f23.y;
            smu[(wm + g    ) * 20 + nt * 4 + t4] = h01;
            smu[(wm + g + 8) * 20 + nt * 4 + t4] = h23;
        }
        rs0 += __shfl_xor_sync(0xffffffffu, rs0, 1);
        rs0 += __shfl_xor_sync(0xffffffffu, rs0, 2);
        rs1 += __shfl_xor_sync(0xffffffffu, rs1, 1);
        rs1 += __shfl_xor_sync(0xffffffffu, rs1, 2);
        l0 = l0 * c0 + rs0;
        l1 = l1 * c1 + rs1;

        #pragma unroll
        for (int dt = 0; dt < 8; dt++) {
            oacc[dt][0] *= c0; oacc[dt][1] *= c0;
            oacc[dt][2] *= c1; oacc[dt][3] *= c1;
        }
        __syncwarp();   // Ps rows are warp-private

        // ---- O += P @ V (m16 x n64, k32 = 2 k16 steps) ----
        unsigned pa[2][4];
        #pragma unroll
        for (int s = 0; s < 2; s++) {
            pa[s][0] = smu[(wm + g    ) * 20 + s * 8 + t4    ];
            pa[s][1] = smu[(wm + g + 8) * 20 + s * 8 + t4    ];
            pa[s][2] = smu[(wm + g    ) * 20 + s * 8 + t4 + 4];
            pa[s][3] = smu[(wm + g + 8) * 20 + s * 8 + t4 + 4];
        }
        #pragma unroll
        for (int dt = 0; dt < 8; dt++) {
            unsigned vf[4];
            *(uint4*)&vf[0] = V4[lb + dt];
            mma_f16(oacc[dt], pa[0], vf[0], vf[1]);
            mma_f16(oacc[dt], pa[1], vf[2], vf[3]);
        }
    }

    // ---- normalize + write out [B, S, H*D] ----
    float inv0 = 1.0f / l0;
    float inv1 = 1.0f / l1;
    int r0 = q0 + wm + g;
    int r1 = r0 + 8;
    #pragma unroll
    for (int dt = 0; dt < 8; dt++) {
        int d = dt * 8 + 2 * t4;
        float2 v0 = make_float2(oacc[dt][0] * inv0, oacc[dt][1] * inv0);
        float2 v1 = make_float2(oacc[dt][2] * inv1, oacc[dt][3] * inv1);
        *(float2*)&out[(b * SS + r0) * HIDN + h * HD + d] = v0;
        *(float2*)&out[(b * SS + r1) * HIDN + h * HD + d] = v1;
    }
}

// ---------------------------------------------------------------------------
extern "C" void kernel_launch(void* const* d_in, const int* in_sizes, int n_in,
                              void* d_out, int out_size) {
    const float* hs   = (const float*)d_in[0];
    const float* mask = (const float*)d_in[1];
    const float* Wq   = (const float*)d_in[2];
    const float* bq   = (const float*)d_in[3];
    const float* Wk   = (const float*)d_in[4];
    const float* bk   = (const float*)d_in[5];
    const float* Wv   = (const float*)d_in[6];
    const float* bv   = (const float*)d_in[7];
    float* out = (float*)d_out;

    static bool attr_set = false;
    if (!attr_set) {
        cudaFuncSetAttribute(qkv_gemm_fp16,
                             cudaFuncAttributeMaxDynamicSharedMemorySize,
                             QKV_SMEM_BYTES);
        cudaFuncSetAttribute(attn_fp16,
                             cudaFuncAttributeMaxDynamicSharedMemorySize,
                             ATTN_SMEM_BYTES);
        attr_set = true;
    }

    sincos_kernel<<<(SS * 32 + 255) / 256, 256>>>();
    round_xh<<<(BB * SS * HIDN / 8) / 256, 256>>>((const float4*)hs);
    wt_transpose_h<<<dim3(HIDN / 32, HIDN / 32, 3), 256>>>(Wq, Wk, Wv);
    qkv_gemm_fp16<<<dim3(30, 32), 256, QKV_SMEM_BYTES>>>(bq, bk, bv);
    rope_kernel_h<<<(BB * NH * SS * 16) / 256, 256>>>();
    repack_kvh<<<dim3(SS / 32, BB * NH), 256>>>();
    attn_fp16<<<dim3(SS / 64, BB * NH), 128, ATTN_SMEM_BYTES>>>(mask, out);
}

// round 12
// speedup vs baseline: 1.4332x; 1.0419x over previous
#include <cuda_runtime.h>
#include <cuda_fp16.h>
#include <cstdint>
#include <math.h>

#define BB 2
#define SS 2048
#define HIDN 1280
#define NH 20
#define HD 64

// Scratch (alloc-free rule: __device__ globals)
__device__ float g_Q[BB*NH*SS*HD];
__device__ float g_K[BB*NH*SS*HD];
__device__ float g_V[BB*NH*SS*HD];
__device__ unsigned g_Qh[BB*NH*SS*HD/2];     // Q fp16 (half2-packed along d)
__device__ unsigned g_Kf[BB*NH*SS*HD/2];     // K fp16, per-lane mma B-frag order
__device__ unsigned g_Vf[BB*NH*SS*HD/2];     // V fp16, per-lane mma B-frag order
__device__ unsigned g_Xh[BB*SS*HIDN/2];      // hidden states fp16
__device__ unsigned g_Wth[3*HIDN*HIDN/2];    // transposed weights fp16 ([n][k])
__device__ float g_cos[SS*32];
__device__ float g_sin[SS*32];

// ---------------------------------------------------------------------------
// helpers
// ---------------------------------------------------------------------------
__device__ __forceinline__ unsigned packh2(float x, float y) {
    __half2 h = __floats2half2_rn(x, y);
    return *reinterpret_cast<unsigned*>(&h);
}

__device__ __forceinline__ void mma_f16(float c[4], const unsigned a[4],
                                        unsigned b0, unsigned b1) {
    asm volatile(
        "mma.sync.aligned.m16n8k16.row.col.f32.f16.f16.f32 "
        "{%0,%1,%2,%3}, {%4,%5,%6,%7}, {%8,%9}, {%0,%1,%2,%3};"
        : "+f"(c[0]), "+f"(c[1]), "+f"(c[2]), "+f"(c[3])
        : "r"(a[0]), "r"(a[1]), "r"(a[2]), "r"(a[3]),
          "r"(b0), "r"(b1));
}

__device__ __forceinline__ void ldm_x4(unsigned r[4], unsigned addr) {
    asm volatile(
        "ldmatrix.sync.aligned.m8n8.x4.shared.b16 {%0,%1,%2,%3}, [%4];"
        : "=r"(r[0]), "=r"(r[1]), "=r"(r[2]), "=r"(r[3])
        : "r"(addr));
}

__device__ __forceinline__ void cp16(unsigned int dst, const void* src) {
    asm volatile("cp.async.cg.shared.global [%0], [%1], 16;\n"
                 :: "r"(dst), "l"(src));
}
__device__ __forceinline__ void cp_commit() {
    asm volatile("cp.async.commit_group;\n" ::: "memory");
}
template <int N>
__device__ __forceinline__ void cp_wait() {
    asm volatile("cp.async.wait_group %0;\n" :: "n"(N) : "memory");
}

// ---------------------------------------------------------------------------
// RoPE cos/sin table
// ---------------------------------------------------------------------------
__global__ void sincos_kernel() {
    int idx = blockIdx.x * blockDim.x + threadIdx.x;
    if (idx >= SS * 32) return;
    int j = idx & 31;
    int s = idx >> 5;
    double invf = exp(-((double)j / 32.0) * log(10000.0));
    double a = (double)s * invf;
    g_cos[idx] = (float)cos(a);
    g_sin[idx] = (float)sin(a);
}

// ---------------------------------------------------------------------------
// Convert hidden states to fp16 (half2-packed)
// ---------------------------------------------------------------------------
__global__ __launch_bounds__(256) void round_xh(const float4* __restrict__ X) {
    int i = blockIdx.x * blockDim.x + threadIdx.x;   // uint4 index
    float4 a = X[2 * i], b = X[2 * i + 1];
    uint4 o;
    o.x = packh2(a.x, a.y);
    o.y = packh2(a.z, a.w);
    o.z = packh2(b.x, b.y);
    o.w = packh2(b.z, b.w);
    ((uint4*)g_Xh)[i] = o;
}

// ---------------------------------------------------------------------------
// Transpose + fp16-pack the three weight matrices: g_Wth[which][n][k]=W[k][n]
// ---------------------------------------------------------------------------
__global__ __launch_bounds__(256) void wt_transpose_h(
    const float* __restrict__ Wq,
    const float* __restrict__ Wk,
    const float* __restrict__ Wv)
{
    __shared__ float t[32][33];
    const float* W = (blockIdx.z == 0) ? Wq : (blockIdx.z == 1 ? Wk : Wv);
    unsigned* Out = g_Wth + (size_t)blockIdx.z * (HIDN * HIDN / 2);
    int k0 = blockIdx.x * 32, n0 = blockIdx.y * 32;
    int tx = threadIdx.x & 31, ty = threadIdx.x >> 5;   // 32 x 8
    #pragma unroll
    for (int p = 0; p < 4; p++) {
        int k = ty + p * 8;
        t[k][tx] = W[(k0 + k) * HIDN + n0 + tx];
    }
    __syncthreads();
    int nb = threadIdx.x >> 4;      // 0..15
    int kp = threadIdx.x & 15;      // k-pair 0..15
    #pragma unroll
    for (int p = 0; p < 2; p++) {
        int n = nb + p * 16;
        Out[(size_t)(n0 + n) * (HIDN / 2) + k0 / 2 + kp] =
            packh2(t[2 * kp][n], t[2 * kp + 1][n]);
    }
}

// ---------------------------------------------------------------------------
// Fused QKV projection GEMM — fp16 mma.m16n8k16 + ldmatrix + cp.async pipeline.
// Block tile 128x128, 8 warps (2m x 4n), warp tile 64x32.
// K chunk = 64 halves (32 uint32/row), 20 chunks.
// Dynamic smem (uint32): A0 [0,4608) A1 [4608,9216) B0 [9216,13824) B1 [13824,18432)
// Row stride 36 uint32 = 144B (ldmatrix phases conflict-free).
// ---------------------------------------------------------------------------
#define QKV_SMEM_BYTES (18432 * 4)

__global__ __launch_bounds__(256, 2) void qkv_gemm_fp16(
    const float* __restrict__ bq,
    const float* __restrict__ bk,
    const float* __restrict__ bv)
{
    extern __shared__ unsigned smu[];

    const int n0g   = blockIdx.x * 128;
    const int m0    = blockIdx.y * 128;
    const int which = n0g / HIDN;
    const int ncol0 = n0g % HIDN;

    const unsigned* Wp = g_Wth + (size_t)which * (HIDN * HIDN / 2);
    const float* bias  = (which == 0) ? bq : (which == 1 ? bk : bv);
    float*       Out   = (which == 0) ? g_Q : (which == 1 ? g_K : g_V);

    const int tid  = threadIdx.x;
    const int lane = tid & 31;
    const int warp = tid >> 5;
    const int wm   = (warp & 1) * 64;
    const int wn   = (warp >> 1) * 32;
    const int g    = lane >> 2;
    const int t4   = lane & 3;

    const unsigned int sbase = (unsigned int)__cvta_generic_to_shared(smu);
    const int st_row = tid & 127;        // staged row
    const int st_seg = tid >> 7;         // 0/1: which 16-uint32 half of row

    // ldmatrix per-lane byte offsets (within a buffer)
    // A x4 (m16 x k16 at (mt, s)): lanes 0-15 rows wm+mt*16+(lane&15), col s*8
    //                              lanes 16-31 same rows, col s*8+4 (u32)
    const unsigned a_loff =
        ((unsigned)((wm + (lane & 15)) * 36 + (lane >> 4) * 4)) * 4;
    // B x4 (two n8 frags at (ntp, s)): row wn+ntp*16+(lane>>4)*8+(lane&7),
    //                                  col s*8 + ((lane>>3)&1)*4
    const unsigned b_loff =
        ((unsigned)((wn + (lane >> 4) * 8 + (lane & 7)) * 36 +
                    ((lane >> 3) & 1) * 4)) * 4;

    float acc[4][4][4];
    #pragma unroll
    for (int mt = 0; mt < 4; mt++)
        #pragma unroll
        for (int nt = 0; nt < 4; nt++)
            #pragma unroll
            for (int i = 0; i < 4; i++) acc[mt][nt][i] = 0.0f;

    const unsigned* srcA = g_Xh + (size_t)(m0 + st_row) * (HIDN / 2);
    const unsigned* srcB = Wp + (size_t)(ncol0 + st_row) * (HIDN / 2);

    // Prologue: stage chunk 0 into buffer 0
    {
        #pragma unroll
        for (int u = 0; u < 4; u++) {
            int o = st_seg * 16 + u * 4;
            cp16(sbase + (st_row * 36 + o) * 4, srcA + o);
            cp16(sbase + (9216 + st_row * 36 + o) * 4, srcB + o);
        }
        cp_commit();
    }

    for (int kt = 0; kt < 20; kt++) {
        const int buf = kt & 1;
        cp_wait<0>();
        __syncthreads();   // chunk kt visible + all done reading buf^1

        if (kt < 19) {
            const int k32 = (kt + 1) * 32;
            const int ao = (buf ^ 1) * 4608;
            const int bo = 9216 + (buf ^ 1) * 4608;
            #pragma unroll
            for (int u = 0; u < 4; u++) {
                int o = st_seg * 16 + u * 4;
                cp16(sbase + (ao + st_row * 36 + o) * 4, srcA + k32 + o);
                cp16(sbase + (bo + st_row * 36 + o) * 4, srcB + k32 + o);
            }
            cp_commit();
        }

        const unsigned Abase = sbase + buf * 4608 * 4 + a_loff;
        const unsigned Bbase = sbase + (9216 + buf * 4608) * 4 + b_loff;

        #pragma unroll
        for (int s = 0; s < 4; s++) {        // 4 k16 steps per chunk
            unsigned a[4][4];
            #pragma unroll
            for (int mt = 0; mt < 4; mt++)
                ldm_x4(a[mt], Abase + (mt * 2304 + s * 32));   // mt*16*36*4, s*8*4
            unsigned bf[2][4];
            #pragma unroll
            for (int ntp = 0; ntp < 2; ntp++)
                ldm_x4(bf[ntp], Bbase + (ntp * 2304 + s * 32));
            #pragma unroll
            for (int nt = 0; nt < 4; nt++) {
                unsigned b0 = bf[nt >> 1][(nt & 1) * 2];
                unsigned b1 = bf[nt >> 1][(nt & 1) * 2 + 1];
                #pragma unroll
                for (int mt = 0; mt < 4; mt++)
                    mma_f16(acc[mt][nt], a[mt], b0, b1);
            }
        }
    }

    // Epilogue: bias + scatter into [B, H, S, D] (fp32)
    #pragma unroll
    for (int mt = 0; mt < 4; mt++) {
        #pragma unroll
        for (int nt = 0; nt < 4; nt++) {
            int col = ncol0 + wn + nt * 8 + t4 * 2;
            int h = col >> 6;
            int d = col & 63;
            float bi0 = bias[col];
            float bi1 = bias[col + 1];
            #pragma unroll
            for (int rh = 0; rh < 2; rh++) {
                int m = m0 + wm + mt * 16 + g + rh * 8;
                int b = m >> 11;
                int s = m & 2047;
                float2 v;
                v.x = acc[mt][nt][rh * 2 + 0] + bi0;
                v.y = acc[mt][nt][rh * 2 + 1] + bi1;
                *(float2*)&Out[(((b * NH + h) * SS) + s) * HD + d] = v;
            }
        }
    }
}

// ---------------------------------------------------------------------------
// RoPE: Q -> rotated, scaled, fp16-packed into g_Qh.
//       K -> rotated in place (fp32; repack converts to fp16).
// ---------------------------------------------------------------------------
__global__ __launch_bounds__(256) void rope_kernel_h() {
    int idx = blockIdx.x * blockDim.x + threadIdx.x;   // < BB*NH*SS*16
    int j2 = idx & 15;
    int s  = (idx >> 4) & (SS - 1);
    int bh = idx >> 15;
    int j  = 2 * j2;
    float c0 = g_cos[(s << 5) + j],     c1 = g_cos[(s << 5) + j + 1];
    float s0 = g_sin[(s << 5) + j],     s1 = g_sin[(s << 5) + j + 1];
    int base = (bh * SS + s) * HD;
    const float scale = 0.125f;

    float q1x = g_Q[base + j],      q1y = g_Q[base + j + 1];
    float q2x = g_Q[base + j + 32], q2y = g_Q[base + j + 33];
    g_Qh[(base >> 1) + j2]      = packh2((q1x * c0 - q2x * s0) * scale,
                                         (q1y * c1 - q2y * s1) * scale);
    g_Qh[(base >> 1) + 16 + j2] = packh2((q2x * c0 + q1x * s0) * scale,
                                         (q2y * c1 + q1y * s1) * scale);

    float k1x = g_K[base + j],      k1y = g_K[base + j + 1];
    float k2x = g_K[base + j + 32], k2y = g_K[base + j + 33];
    g_K[base + j]      = k1x * c0 - k2x * s0;
    g_K[base + j + 1]  = k1y * c1 - k2y * s1;
    g_K[base + j + 32] = k2x * c0 + k1x * s0;
    g_K[base + j + 33] = k2y * c1 + k1y * s1;
}

// ---------------------------------------------------------------------------
// Repack K and V (fp32) into fp16 per-lane mma B-fragment order.
// ---------------------------------------------------------------------------
__global__ __launch_bounds__(256) void repack_kvh() {
    __shared__ float Ks[32][68];
    __shared__ float Vs[32][68];

    const int tile = blockIdx.x;
    const int bh   = blockIdx.y;
    const float* Kb = g_K + ((size_t)bh * SS + tile * 32) * HD;
    const float* Vb = g_V + ((size_t)bh * SS + tile * 32) * HD;

    const int t = threadIdx.x;
    const int r0 = t >> 4;
    const int c0 = (t & 15) * 4;

    #pragma unroll
    for (int p = 0; p < 2; p++) {
        int r = r0 + 16 * p;
        *(float4*)&Ks[r][c0] = *(const float4*)&Kb[r * HD + c0];
        *(float4*)&Vs[r][c0] = *(const float4*)&Vb[r * HD + c0];
    }
    __syncthreads();

    const int lane = t >> 3;
    const int q    = t & 7;             // handles vi = 4q .. 4q+3
    const int g    = lane >> 2;
    const int t4   = lane & 3;
    const size_t rowidx = ((size_t)bh * 64 + tile) * 32 + lane;

    unsigned ok[4], ov[4];
    #pragma unroll
    for (int i = 0; i < 4; i++) {
        int vi = q * 4 + i;
        int nt = vi >> 3, r = vi & 7, kc = r >> 1, b = r & 1;
        int d0 = 2 * t4 + 16 * kc + 8 * b;
        ok[i] = packh2(Ks[nt * 8 + g][d0], Ks[nt * 8 + g][d0 + 1]);
        int dt = vi >> 2, r2 = vi & 3, sx = r2 >> 1, bv = r2 & 1;
        int k0 = 2 * t4 + 16 * sx + 8 * bv;
        ov[i] = packh2(Vs[k0][dt * 8 + g], Vs[k0 + 1][dt * 8 + g]);
    }
    ((uint4*)g_Kf)[rowidx * 8 + q] = *(uint4*)&ok[0];
    ((uint4*)g_Vf)[rowidx * 8 + q] = *(uint4*)&ov[0];
}

// ---------------------------------------------------------------------------
// Flash attention, fp16 mma.m16n8k16, cp.async double-buffered fragment K/V.
// (unchanged from R11)
// ---------------------------------------------------------------------------
#define AOFF_K 2304
#define AOFF_V 4608
#define ABUF 1152
#define ATTN_SMEM_BYTES (6912 * 4)

__global__ __launch_bounds__(128) void attn_fp16(
    const float* __restrict__ mask, float* __restrict__ out)
{
    extern __shared__ unsigned smu[];

    const int bh = blockIdx.y;
    const int b  = bh / NH;
    const int h  = bh % NH;
    const int q0 = blockIdx.x * 64;

    const unsigned* Qhb = g_Qh + (size_t)(bh * SS + q0) * 32;
    const unsigned* Kfb = g_Kf + (size_t)bh * 65536;
    const unsigned* Vfb = g_Vf + (size_t)bh * 65536;
    const float2* mk2 = (const float2*)(mask + b * SS);

    const int tid  = threadIdx.x;
    const int lane = tid & 31;
    const int warp = tid >> 5;
    const int g    = lane >> 2;
    const int t4   = lane & 3;
    const int wm   = warp * 16;

    const unsigned int sbase = (unsigned int)__cvta_generic_to_shared(smu);
    const int c_lane = tid >> 2;
    const int c_seg  = tid & 3;

    {
        #pragma unroll
        for (int u = 0; u < 2; u++) {
            int o = c_seg * 8 + u * 4;
            cp16(sbase + (AOFF_K + c_lane * 36 + o) * 4, Kfb + c_lane * 32 + o);
            cp16(sbase + (AOFF_V + c_lane * 36 + o) * 4, Vfb + c_lane * 32 + o);
        }
        cp_commit();
    }

    for (int i = tid; i < 512; i += 128) {
        int row = i >> 3, c4 = (i & 7) * 4;
        *(uint4*)&smu[row * 36 + c4] = ((const uint4*)Qhb)[i];
    }
    __syncthreads();

    unsigned qf[4][4];
    #pragma unroll
    for (int kc = 0; kc < 4; kc++) {
        qf[kc][0] = smu[(wm + g    ) * 36 + kc * 8 + t4    ];
        qf[kc][1] = smu[(wm + g + 8) * 36 + kc * 8 + t4    ];
        qf[kc][2] = smu[(wm + g    ) * 36 + kc * 8 + t4 + 4];
        qf[kc][3] = smu[(wm + g + 8) * 36 + kc * 8 + t4 + 4];
    }

    float oacc[8][4];
    #pragma unroll
    for (int dt = 0; dt < 8; dt++)
        #pragma unroll
        for (int i = 0; i < 4; i++) oacc[dt][i] = 0.0f;
    float m0r = -1e30f, m1r = -1e30f, l0 = 0.0f, l1 = 0.0f;

    for (int it = 0; it < SS / 32; it++) {
        const int buf = it & 1;
        cp_wait<0>();
        __syncthreads();

        if (it < SS / 32 - 1) {
            const unsigned* Kn = Kfb + (it + 1) * 1024;
            const unsigned* Vn = Vfb + (it + 1) * 1024;
            int ko = AOFF_K + (buf ^ 1) * ABUF;
            int vo = AOFF_V + (buf ^ 1) * ABUF;
            #pragma unroll
            for (int u = 0; u < 2; u++) {
                int o = c_seg * 8 + u * 4;
                cp16(sbase + (ko + c_lane * 36 + o) * 4, Kn + c_lane * 32 + o);
                cp16(sbase + (vo + c_lane * 36 + o) * 4, Vn + c_lane * 32 + o);
            }
            cp_commit();
        }

        const uint4* K4 = (const uint4*)(smu + AOFF_K + buf * ABUF);
        const uint4* V4 = (const uint4*)(smu + AOFF_V + buf * ABUF);
        const int lb = lane * 9;

        float sc[4][4];
        #pragma unroll
        for (int nt = 0; nt < 4; nt++)
            #pragma unroll
            for (int i = 0; i < 4; i++) sc[nt][i] = 0.0f;

        #pragma unroll
        for (int nt = 0; nt < 4; nt++) {
            unsigned kf[8];
            *(uint4*)&kf[0] = K4[lb + nt * 2];
            *(uint4*)&kf[4] = K4[lb + nt * 2 + 1];
            #pragma unroll
            for (int kc = 0; kc < 4; kc++)
                mma_f16(sc[nt], qf[kc], kf[kc * 2], kf[kc * 2 + 1]);
        }

        const int k0 = it * 32;
        #pragma unroll
        for (int nt = 0; nt < 4; nt++) {
            float2 mv = __ldg(&mk2[(k0 + nt * 8) / 2 + t4]);
            sc[nt][0] += mv.x; sc[nt][1] += mv.y;
            sc[nt][2] += mv.x; sc[nt][3] += mv.y;
        }
        float rx0 = -1e30f, rx1 = -1e30f;
        #pragma unroll
        for (int nt = 0; nt < 4; nt++) {
            rx0 = fmaxf(rx0, fmaxf(sc[nt][0], sc[nt][1]));
            rx1 = fmaxf(rx1, fmaxf(sc[nt][2], sc[nt][3]));
        }
        rx0 = fmaxf(rx0, __shfl_xor_sync(0xffffffffu, rx0, 1));
        rx0 = fmaxf(rx0, __shfl_xor_sync(0xffffffffu, rx0, 2));
        rx1 = fmaxf(rx1, __shfl_xor_sync(0xffffffffu, rx1, 1));
        rx1 = fmaxf(rx1, __shfl_xor_sync(0xffffffffu, rx1, 2));

        float m0n = fmaxf(m0r, rx0);
        float m1n = fmaxf(m1r, rx1);
        float c0 = __expf(m0r - m0n);
        float c1 = __expf(m1r - m1n);
        m0r = m0n; m1r = m1n;

        float rs0 = 0.0f, rs1 = 0.0f;
        #pragma unroll
        for (int nt = 0; nt < 4; nt++) {
            float p0 = __expf(sc[nt][0] - m0n);
            float p1 = __expf(sc[nt][1] - m0n);
            float p2 = __expf(sc[nt][2] - m1n);
            float p3 = __expf(sc[nt][3] - m1n);
            unsigned h01 = packh2(p0, p1);
            unsigned h23 = packh2(p2, p3);
            float2 f01 = __half22float2(*(__half2*)&h01);
            float2 f23 = __half22float2(*(__half2*)&h23);
            rs0 += f01.x + f01.y;
            rs1 += f23.x + f23.y;
            smu[(wm + g    ) * 20 + nt * 4 + t4] = h01;
            smu[(wm + g + 8) * 20 + nt * 4 + t4] = h23;
        }
        rs0 += __shfl_xor_sync(0xffffffffu, rs0, 1);
        rs0 += __shfl_xor_sync(0xffffffffu, rs0, 2);
        rs1 += __shfl_xor_sync(0xffffffffu, rs1, 1);
        rs1 += __shfl_xor_sync(0xffffffffu, rs1, 2);
        l0 = l0 * c0 + rs0;
        l1 = l1 * c1 + rs1;

        #pragma unroll
        for (int dt = 0; dt < 8; dt++) {
            oacc[dt][0] *= c0; oacc[dt][1] *= c0;
            oacc[dt][2] *= c1; oacc[dt][3] *= c1;
        }
        __syncwarp();

        unsigned pa[2][4];
        #pragma unroll
        for (int s = 0; s < 2; s++) {
            pa[s][0] = smu[(wm + g    ) * 20 + s * 8 + t4    ];
            pa[s][1] = smu[(wm + g + 8) * 20 + s * 8 + t4    ];
            pa[s][2] = smu[(wm + g    ) * 20 + s * 8 + t4 + 4];
            pa[s][3] = smu[(wm + g + 8) * 20 + s * 8 + t4 + 4];
        }
        #pragma unroll
        for (int dt = 0; dt < 8; dt++) {
            unsigned vf[4];
            *(uint4*)&vf[0] = V4[lb + dt];
            mma_f16(oacc[dt], pa[0], vf[0], vf[1]);
            mma_f16(oacc[dt], pa[1], vf[2], vf[3]);
        }
    }

    float inv0 = 1.0f / l0;
    float inv1 = 1.0f / l1;
    int r0 = q0 + wm + g;
    int r1 = r0 + 8;
    #pragma unroll
    for (int dt = 0; dt < 8; dt++) {
        int d = dt * 8 + 2 * t4;
        float2 v0 = make_float2(oacc[dt][0] * inv0, oacc[dt][1] * inv0);
        float2 v1 = make_float2(oacc[dt][2] * inv1, oacc[dt][3] * inv1);
        *(float2*)&out[(b * SS + r0) * HIDN + h * HD + d] = v0;
        *(float2*)&out[(b * SS + r1) * HIDN + h * HD + d] = v1;
    }
}

// ---------------------------------------------------------------------------
extern "C" void kernel_launch(void* const* d_in, const int* in_sizes, int n_in,
                              void* d_out, int out_size) {
    const float* hs   = (const float*)d_in[0];
    const float* mask = (const float*)d_in[1];
    const float* Wq   = (const float*)d_in[2];
    const float* bq   = (const float*)d_in[3];
    const float* Wk   = (const float*)d_in[4];
    const float* bk   = (const float*)d_in[5];
    const float* Wv   = (const float*)d_in[6];
    const float* bv   = (const float*)d_in[7];
    float* out = (float*)d_out;

    static bool attr_set = false;
    if (!attr_set) {
        cudaFuncSetAttribute(qkv_gemm_fp16,
                             cudaFuncAttributeMaxDynamicSharedMemorySize,
                             QKV_SMEM_BYTES);
        cudaFuncSetAttribute(attn_fp16,
                             cudaFuncAttributeMaxDynamicSharedMemorySize,
                             ATTN_SMEM_BYTES);
        attr_set = true;
    }

    sincos_kernel<<<(SS * 32 + 255) / 256, 256>>>();
    round_xh<<<(BB * SS * HIDN / 8) / 256, 256>>>((const float4*)hs);
    wt_transpose_h<<<dim3(HIDN / 32, HIDN / 32, 3), 256>>>(Wq, Wk, Wv);
    qkv_gemm_fp16<<<dim3(30, 32), 256, QKV_SMEM_BYTES>>>(bq, bk, bv);
    rope_kernel_h<<<(BB * NH * SS * 16) / 256, 256>>>();
    repack_kvh<<<dim3(SS / 32, BB * NH), 256>>>();
    attn_fp16<<<dim3(SS / 64, BB * NH), 128, ATTN_SMEM_BYTES>>>(mask, out);
}